// round 1
// baseline (speedup 1.0000x reference)
#include <cuda_runtime.h>
#include <math.h>
#include <stdint.h>

// Problem constants
#define BQ   512
#define LQ   128
#define MQ   6
#define AD   39           // ATOM_DIM
#define BD   10           // BOND_DIM
#define CD   (AD + BD)    // 49, concat dim
#define FPD  256
#define NATOMS (BQ * LQ)  // 65536

// ---------------------------------------------------------------------------
// Scratch (device globals: allocation-free rule)
// ---------------------------------------------------------------------------
__device__ float g_af[NATOMS * FPD];    // atom_feature (leaky)   67 MB
__device__ float g_s[NATOMS * FPD];     // sum_m a_m * nf_m       67 MB
__device__ float g_ctx[NATOMS * FPD];   // elu(context)           67 MB
__device__ float g_asum[NATOMS];        // sum_m a_m

__device__ __forceinline__ float leakyf(float x) { return x > 0.f ? x : 0.01f * x; }
__device__ __forceinline__ float sigmf(float x)  { return 1.f / (1.f + expf(-x)); }

// ---------------------------------------------------------------------------
// Kernel 1: fused gather + atom/neighbor projections + attention + weighted sum
//   outputs: g_af, g_s, g_asum
// Weights (W_atom, W_nbr, W_align) live in SMEM transposed [k][f], loaded once
// per CTA; atoms streamed. 256 threads, thread == feature.
// ---------------------------------------------------------------------------
#define K1_ATOMS 32
// smem floats: Wa 39*256 + Wn 49*256 + wal 512 + acts 6*52 + atomrow 40 + red 56 + padf 6
#define K1_F (AD*FPD + CD*FPD + 2*FPD + MQ*52 + 40 + 56 + 6)
#define K1_SMEM (K1_F*4 + 16*4)   // + ints for indices

__global__ void __launch_bounds__(256, 2) attn_kernel(
    const float* __restrict__ atom_list, const float* __restrict__ bond_list,
    const int*   __restrict__ adeg,      const int*   __restrict__ bdeg,
    const float* __restrict__ W_atom,    const float* __restrict__ b_atom,
    const float* __restrict__ W_nbr,     const float* __restrict__ b_nbr,
    const float* __restrict__ W_align,   const float* __restrict__ b_align)
{
    extern __shared__ float smem[];
    float* Wa      = smem;                    // [39][256] (k-major)
    float* Wn      = Wa + AD * FPD;           // [49][256]
    float* wal     = Wn + CD * FPD;           // [512]
    float* acts    = wal + 2 * FPD;           // [6][52]
    float* atomrow = acts + MQ * 52;          // [40]
    float* red     = atomrow + 40;            // [8][7]
    float* padf    = red + 56;                // [6]
    int*   idxA    = (int*)(padf + 6);        // [6]
    int*   idxB    = idxA + 6;                // [6]

    const int tid = threadIdx.x;
    const int f   = tid;

    // --- load weights (transposed) once per CTA ---
    for (int i = tid; i < AD * FPD; i += 256) {
        int ff = i / AD, k = i % AD;
        Wa[k * FPD + ff] = W_atom[i];
    }
    for (int i = tid; i < CD * FPD; i += 256) {
        int ff = i / CD, k = i % CD;
        Wn[k * FPD + ff] = W_nbr[i];
    }
    for (int i = tid; i < 2 * FPD; i += 256) wal[i] = W_align[i];

    const float ba  = b_atom[f];
    const float bn  = b_nbr[f];
    const float bal = b_align[0];
    __syncthreads();

    const float wal1 = wal[f];
    const float wal2 = wal[FPD + f];
    const int   warp = tid >> 5;
    const int   lane = tid & 31;

    const int base = blockIdx.x * K1_ATOMS;

    for (int ai = 0; ai < K1_ATOMS; ai++) {
        const int atom = base + ai;
        const int bmol = atom / LQ;

        __syncthreads();   // protect smem reuse from previous iteration
        // phase 1: indices + pad flags
        if (tid < MQ) {
            int ia = adeg[atom * MQ + tid];
            idxA[tid] = ia;
            padf[tid] = (ia == LQ - 1) ? 1.f : 0.f;
        } else if (tid < 2 * MQ) {
            idxB[tid - MQ] = bdeg[atom * MQ + tid - MQ];
        }
        __syncthreads();
        // phase 2: stage activations (gather)
        for (int i = tid; i < AD + MQ * CD; i += 256) {
            if (i < AD) {
                atomrow[i] = atom_list[atom * AD + i];
            } else {
                int j = i - AD;
                int m = j / CD, c = j % CD;
                float v;
                if (c < AD) v = atom_list[(bmol * LQ + idxA[m]) * AD + c];
                else        v = bond_list[(bmol * LQ + idxB[m]) * BD + (c - AD)];
                acts[m * 52 + c] = v;
            }
        }
        __syncthreads();

        // phase 3: projections
        float af = ba;
        #pragma unroll
        for (int k = 0; k < AD; k++) af += Wa[k * FPD + f] * atomrow[k];
        af = leakyf(af);

        float nf[MQ];
        #pragma unroll
        for (int m = 0; m < MQ; m++) nf[m] = bn;
        #pragma unroll 7
        for (int k = 0; k < CD; k++) {
            float w = Wn[k * FPD + f];
            #pragma unroll
            for (int m = 0; m < MQ; m++) nf[m] += w * acts[m * 52 + k];
        }
        #pragma unroll
        for (int m = 0; m < MQ; m++) nf[m] = leakyf(nf[m]);

        // phase 4: align-score dot products (reduce over features)
        float v[7];
        v[0] = af * wal1;
        #pragma unroll
        for (int m = 0; m < MQ; m++) v[1 + m] = nf[m] * wal2;
        #pragma unroll
        for (int off = 16; off > 0; off >>= 1) {
            #pragma unroll
            for (int j = 0; j < 7; j++)
                v[j] += __shfl_down_sync(0xffffffffu, v[j], off);
        }
        if (lane == 0) {
            #pragma unroll
            for (int j = 0; j < 7; j++) red[warp * 7 + j] = v[j];
        }
        __syncthreads();

        // phase 5: softmax (computed redundantly per thread from smem broadcasts)
        float sums[7];
        #pragma unroll
        for (int j = 0; j < 7; j++) {
            float s = 0.f;
            #pragma unroll
            for (int w = 0; w < 8; w++) s += red[w * 7 + j];
            sums[j] = s;
        }
        float sc[MQ], mx = -INFINITY;
        #pragma unroll
        for (int m = 0; m < MQ; m++) {
            float s = leakyf(sums[0] + sums[1 + m] + bal);
            if (padf[m] > 0.5f) s += -9e8f;
            sc[m] = s;
            mx = fmaxf(mx, s);
        }
        float e[MQ], se = 0.f;
        #pragma unroll
        for (int m = 0; m < MQ; m++) { e[m] = expf(sc[m] - mx); se += e[m]; }
        float inv = 1.f / se;
        float asum = 0.f, sf = 0.f;
        #pragma unroll
        for (int m = 0; m < MQ; m++) {
            float a = e[m] * inv;
            if (padf[m] > 0.5f) a = 0.f;
            asum += a;
            sf += a * nf[m];
        }
        g_s[atom * FPD + f]  = sf;
        g_af[atom * FPD + f] = af;
        if (tid == 0) g_asum[atom] = asum;
    }
}

// ---------------------------------------------------------------------------
// Kernel 2a: ctx = elu( s @ W_attend^T + asum * b_attend )
// 64x64 tile per CTA, 4x4 microtile per thread, K-chunks of 16.
// ---------------------------------------------------------------------------
__global__ void __launch_bounds__(256) ctx_kernel(
    const float* __restrict__ Watt, const float* __restrict__ batt)
{
    __shared__ float As[16][68];
    __shared__ float Bs[16][68];
    const int tid = threadIdx.x;
    const int m0 = blockIdx.x * 64;
    const int n0 = blockIdx.y * 64;
    const int tx = tid & 15, ty = tid >> 4;

    float acc[4][4] = {};

    const int lkk = tid & 15, la = tid >> 4;
    for (int k0 = 0; k0 < FPD; k0 += 16) {
        __syncthreads();
        #pragma unroll
        for (int p = 0; p < 4; p++) {
            As[lkk][la + p * 16] = g_s[(m0 + la + p * 16) * FPD + k0 + lkk];
            Bs[lkk][la + p * 16] = Watt[(n0 + la + p * 16) * FPD + k0 + lkk];
        }
        __syncthreads();
        #pragma unroll
        for (int kk = 0; kk < 16; kk++) {
            float4 av = *(const float4*)&As[kk][ty * 4];
            float4 bv = *(const float4*)&Bs[kk][tx * 4];
            acc[0][0] += av.x*bv.x; acc[0][1] += av.x*bv.y; acc[0][2] += av.x*bv.z; acc[0][3] += av.x*bv.w;
            acc[1][0] += av.y*bv.x; acc[1][1] += av.y*bv.y; acc[1][2] += av.y*bv.z; acc[1][3] += av.y*bv.w;
            acc[2][0] += av.z*bv.x; acc[2][1] += av.z*bv.y; acc[2][2] += av.z*bv.z; acc[2][3] += av.z*bv.w;
            acc[3][0] += av.w*bv.x; acc[3][1] += av.w*bv.y; acc[3][2] += av.w*bv.z; acc[3][3] += av.w*bv.w;
        }
    }

    float asv[4], bav[4];
    #pragma unroll
    for (int i = 0; i < 4; i++) asv[i] = g_asum[m0 + ty * 4 + i];
    #pragma unroll
    for (int j = 0; j < 4; j++) bav[j] = batt[n0 + tx * 4 + j];

    #pragma unroll
    for (int i = 0; i < 4; i++) {
        float4 o;
        float t0 = acc[i][0] + asv[i] * bav[0];
        float t1 = acc[i][1] + asv[i] * bav[1];
        float t2 = acc[i][2] + asv[i] * bav[2];
        float t3 = acc[i][3] + asv[i] * bav[3];
        o.x = t0 > 0.f ? t0 : expm1f(t0);
        o.y = t1 > 0.f ? t1 : expm1f(t1);
        o.z = t2 > 0.f ? t2 : expm1f(t2);
        o.w = t3 > 0.f ? t3 : expm1f(t3);
        *(float4*)&g_ctx[(m0 + ty * 4 + i) * FPD + n0 + tx * 4] = o;
    }
}

// ---------------------------------------------------------------------------
// Kernel 2b: 6-gate interleaved GEMM + fused GRU epilogue + ReLU.
//   gates 0..2: ctx @ W_ih[g*256+f, :]^T     gates 3..5: af @ W_hh[g*256+f, :]^T
// Tile: 64 atoms x 32 features; thread: 4 atoms x 2 features x 6 gates.
// ---------------------------------------------------------------------------
__global__ void __launch_bounds__(256) gru_kernel(
    const float* __restrict__ W_ih, const float* __restrict__ b_ih,
    const float* __restrict__ W_hh, const float* __restrict__ b_hh,
    float* __restrict__ out)
{
    __shared__ float Ac[16][68];
    __shared__ float Ah[16][68];
    __shared__ float Bs[16][194];   // [kk][g*32 + f], padded row
    const int tid = threadIdx.x;
    const int m0 = blockIdx.x * 64;
    const int f0 = blockIdx.y * 32;
    const int tx = tid & 15, ty = tid >> 4;

    float acc[4][2][6] = {};

    const int lkk = tid & 15, la = tid >> 4;
    for (int k0 = 0; k0 < FPD; k0 += 16) {
        __syncthreads();
        #pragma unroll
        for (int p = 0; p < 4; p++) {
            Ac[lkk][la + p * 16] = g_ctx[(m0 + la + p * 16) * FPD + k0 + lkk];
            Ah[lkk][la + p * 16] = g_af [(m0 + la + p * 16) * FPD + k0 + lkk];
        }
        #pragma unroll
        for (int p = 0; p < 12; p++) {
            int i    = tid + p * 256;        // < 3072
            int kk2  = i & 15;
            int rest = i >> 4;               // 0..191
            int fcol = rest & 31;
            int g    = rest >> 5;            // 0..5
            const float* W = (g < 3) ? W_ih : W_hh;
            int row = (g % 3) * FPD + f0 + fcol;
            Bs[kk2][g * 32 + fcol] = W[row * FPD + k0 + kk2];
        }
        __syncthreads();
        #pragma unroll
        for (int kk = 0; kk < 16; kk++) {
            float4 ac = *(const float4*)&Ac[kk][ty * 4];
            float4 ah = *(const float4*)&Ah[kk][ty * 4];
            #pragma unroll
            for (int g = 0; g < 6; g++) {
                float2 b2 = *(const float2*)&Bs[kk][g * 32 + tx * 2];
                float ax = (g < 3) ? ac.x : ah.x;
                float ay = (g < 3) ? ac.y : ah.y;
                float az = (g < 3) ? ac.z : ah.z;
                float aw = (g < 3) ? ac.w : ah.w;
                acc[0][0][g] += ax * b2.x;  acc[0][1][g] += ax * b2.y;
                acc[1][0][g] += ay * b2.x;  acc[1][1][g] += ay * b2.y;
                acc[2][0][g] += az * b2.x;  acc[2][1][g] += az * b2.y;
                acc[3][0][g] += aw * b2.x;  acc[3][1][g] += aw * b2.y;
            }
        }
    }

    // GRU epilogue: r = sig(i_r+h_r); z = sig(i_z+h_z); n = tanh(i_n + r*h_n)
    #pragma unroll
    for (int j = 0; j < 2; j++) {
        int fg = f0 + tx * 2 + j;
        float bir = b_ih[fg], biz = b_ih[FPD + fg], bin_ = b_ih[2 * FPD + fg];
        float bhr = b_hh[fg], bhz = b_hh[FPD + fg], bhn  = b_hh[2 * FPD + fg];
        #pragma unroll
        for (int i = 0; i < 4; i++) {
            int atom = m0 + ty * 4 + i;
            float h  = g_af[atom * FPD + fg];
            float r  = sigmf(acc[i][j][0] + bir + acc[i][j][3] + bhr);
            float z  = sigmf(acc[i][j][1] + biz + acc[i][j][4] + bhz);
            float n  = tanhf(acc[i][j][2] + bin_ + r * (acc[i][j][5] + bhn));
            float hv = (1.f - z) * n + z * h;
            out[atom * FPD + fg] = fmaxf(hv, 0.f);
        }
    }
}

// ---------------------------------------------------------------------------
// Launcher
// ---------------------------------------------------------------------------
extern "C" void kernel_launch(void* const* d_in, const int* in_sizes, int n_in,
                              void* d_out, int out_size)
{
    const float* atom_list = (const float*)d_in[0];
    const float* bond_list = (const float*)d_in[1];
    const int*   adeg      = (const int*)  d_in[2];
    const int*   bdeg      = (const int*)  d_in[3];
    // d_in[4] = atom_mask (unused by the reference)
    const float* W_atom   = (const float*)d_in[5];
    const float* b_atom   = (const float*)d_in[6];
    const float* W_nbr    = (const float*)d_in[7];
    const float* b_nbr    = (const float*)d_in[8];
    const float* W_align  = (const float*)d_in[9];
    const float* b_align  = (const float*)d_in[10];
    const float* W_attend = (const float*)d_in[11];
    const float* b_attend = (const float*)d_in[12];
    const float* W_ih     = (const float*)d_in[13];
    const float* b_ih     = (const float*)d_in[14];
    const float* W_hh     = (const float*)d_in[15];
    const float* b_hh     = (const float*)d_in[16];
    float* out = (float*)d_out;

    (void)in_sizes; (void)n_in; (void)out_size;

    cudaFuncSetAttribute(attn_kernel, cudaFuncAttributeMaxDynamicSharedMemorySize, K1_SMEM);

    attn_kernel<<<NATOMS / K1_ATOMS, 256, K1_SMEM>>>(
        atom_list, bond_list, adeg, bdeg,
        W_atom, b_atom, W_nbr, b_nbr, W_align, b_align);

    dim3 g2a(NATOMS / 64, FPD / 64);
    ctx_kernel<<<g2a, 256>>>(W_attend, b_attend);

    dim3 g2b(NATOMS / 64, FPD / 32);
    gru_kernel<<<g2b, 256>>>(W_ih, b_ih, W_hh, b_hh, out);
}

// round 5
// speedup vs baseline: 1.4747x; 1.4747x over previous
#include <cuda_runtime.h>
#include <cuda_bf16.h>
#include <math.h>
#include <stdint.h>

// Problem constants
#define BQ   512
#define LQ   128
#define MQ   6
#define AD   39
#define BD   10
#define CD   49
#define FPD  256
#define NATOMS (BQ * LQ)   // 65536

// ---------------------------------------------------------------------------
// Device-global scratch (allocation-free rule)
// ---------------------------------------------------------------------------
__device__ __align__(16) float g_af[NATOMS * FPD];
__device__ __align__(16) float g_asum[NATOMS];
__device__ __align__(16) __nv_bfloat16 g_s_hi[NATOMS * FPD],  g_s_lo[NATOMS * FPD];
__device__ __align__(16) __nv_bfloat16 g_af_hi[NATOMS * FPD], g_af_lo[NATOMS * FPD];
__device__ __align__(16) __nv_bfloat16 g_cx_hi[NATOMS * FPD], g_cx_lo[NATOMS * FPD];
__device__ __align__(16) __nv_bfloat16 g_Wat_h[FPD * FPD],     g_Wat_l[FPD * FPD];
__device__ __align__(16) __nv_bfloat16 g_Wih_h[3 * FPD * FPD], g_Wih_l[3 * FPD * FPD];
__device__ __align__(16) __nv_bfloat16 g_Whh_h[3 * FPD * FPD], g_Whh_l[3 * FPD * FPD];

// ---------------------------------------------------------------------------
// Helpers
// ---------------------------------------------------------------------------
__device__ __forceinline__ uint32_t s2u(const void* p) {
    uint32_t a;
    asm("{ .reg .u64 t; cvta.to.shared.u64 t, %1; cvt.u32.u64 %0, t; }" : "=r"(a) : "l"(p));
    return a;
}
// D += A*B, m16n8k16 bf16. Fragment spec (PTX ISA):
//  a0=(r,2q) a1=(r+8,2q) a2=(r,2q+8) a3=(r+8,2q+8); b0=(n,2q) b1=(n,2q+8);
//  c0=(r,2q) c1=(r,2q+1) c2=(r+8,2q) c3=(r+8,2q+1);  r=lane>>2, q=lane&3.
__device__ __forceinline__ void mma16816(float* c, const uint32_t* a, const uint32_t* b) {
    asm volatile("mma.sync.aligned.m16n8k16.row.col.f32.bf16.bf16.f32 "
        "{%0,%1,%2,%3}, {%4,%5,%6,%7}, {%8,%9}, {%0,%1,%2,%3};"
        : "+f"(c[0]), "+f"(c[1]), "+f"(c[2]), "+f"(c[3])
        : "r"(a[0]), "r"(a[1]), "r"(a[2]), "r"(a[3]), "r"(b[0]), "r"(b[1]));
}
__device__ __forceinline__ void cpa16(uint32_t d, const void* s) {
    asm volatile("cp.async.cg.shared.global [%0], [%1], 16;" :: "r"(d), "l"(s) : "memory");
}
#define CP_COMMIT() asm volatile("cp.async.commit_group;" ::: "memory")
#define CP_WAIT1()  asm volatile("cp.async.wait_group 1;" ::: "memory")
#define CP_WAIT0()  asm volatile("cp.async.wait_group 0;" ::: "memory")

__device__ __forceinline__ float leakyf(float x) { return x > 0.f ? x : 0.01f * x; }
__device__ __forceinline__ float sigmf(float x)  { return 1.f / (1.f + expf(-x)); }
__device__ __forceinline__ void split2(float v, __nv_bfloat16& h, __nv_bfloat16& l) {
    h = __float2bfloat16(v);
    l = __float2bfloat16(v - __bfloat162float(h));
}
__device__ __forceinline__ uint32_t pk2(__nv_bfloat16 a, __nv_bfloat16 b) {
    return (uint32_t)__bfloat16_as_ushort(a) | ((uint32_t)__bfloat16_as_ushort(b) << 16);
}

// Arithmetic fragment loads from word-tiles with 20-word (80B) row stride.
// Tile layout: w[row][wq] = packed bf16 pair (elem 2*wq, 2*wq+1), wq 0..15.
__device__ __forceinline__ void ldA(uint32_t* a, const uint32_t* w, int rr, int q) {
    a[0] = w[rr * 20 + q];
    a[1] = w[(rr + 8) * 20 + q];
    a[2] = w[rr * 20 + q + 4];
    a[3] = w[(rr + 8) * 20 + q + 4];
}
__device__ __forceinline__ void ldB(uint32_t* b, const uint32_t* w, int nn, int q) {
    b[0] = w[nn * 20 + q];
    b[1] = w[nn * 20 + q + 4];
}

// ---------------------------------------------------------------------------
// Kernel 0: split weights to bf16 hi/lo pairs
// ---------------------------------------------------------------------------
__global__ void prep_w(const float* __restrict__ Wat, const float* __restrict__ Wih,
                       const float* __restrict__ Whh) {
    int i = blockIdx.x * 256 + threadIdx.x;
    if (i < FPD * FPD)     split2(Wat[i], g_Wat_h[i], g_Wat_l[i]);
    if (i < 3 * FPD * FPD) {
        split2(Wih[i], g_Wih_h[i], g_Wih_l[i]);
        split2(Whh[i], g_Whh_h[i], g_Whh_l[i]);
    }
}

// ---------------------------------------------------------------------------
// Kernel 1: fused gather + projections + attention — R1-proven version,
// only the output stores changed to emit bf16 hi/lo splits.
// ---------------------------------------------------------------------------
#define K1_ATOMS 32
#define K1_F (AD*FPD + CD*FPD + 2*FPD + MQ*52 + 40 + 56 + 6)
#define K1_SMEM (K1_F*4 + 16*4)

__global__ void __launch_bounds__(256, 2) attn_kernel(
    const float* __restrict__ atom_list, const float* __restrict__ bond_list,
    const int*   __restrict__ adeg,      const int*   __restrict__ bdeg,
    const float* __restrict__ W_atom,    const float* __restrict__ b_atom,
    const float* __restrict__ W_nbr,     const float* __restrict__ b_nbr,
    const float* __restrict__ W_align,   const float* __restrict__ b_align)
{
    extern __shared__ float smem[];
    float* Wa      = smem;                    // [39][256] (k-major)
    float* Wn      = Wa + AD * FPD;           // [49][256]
    float* wal     = Wn + CD * FPD;           // [512]
    float* acts    = wal + 2 * FPD;           // [6][52]
    float* atomrow = acts + MQ * 52;          // [40]
    float* red     = atomrow + 40;            // [8][7]
    float* padf    = red + 56;                // [6]
    int*   idxA    = (int*)(padf + 6);        // [6]
    int*   idxB    = idxA + 6;                // [6]

    const int tid = threadIdx.x;
    const int f   = tid;

    for (int i = tid; i < AD * FPD; i += 256) {
        int ff = i / AD, k = i % AD;
        Wa[k * FPD + ff] = W_atom[i];
    }
    for (int i = tid; i < CD * FPD; i += 256) {
        int ff = i / CD, k = i % CD;
        Wn[k * FPD + ff] = W_nbr[i];
    }
    for (int i = tid; i < 2 * FPD; i += 256) wal[i] = W_align[i];

    const float ba  = b_atom[f];
    const float bn  = b_nbr[f];
    const float bal = b_align[0];
    __syncthreads();

    const float wal1 = wal[f];
    const float wal2 = wal[FPD + f];
    const int   warp = tid >> 5;
    const int   lane = tid & 31;

    const int base = blockIdx.x * K1_ATOMS;

    for (int ai = 0; ai < K1_ATOMS; ai++) {
        const int atom = base + ai;
        const int bmol = atom / LQ;

        __syncthreads();
        if (tid < MQ) {
            int ia = adeg[atom * MQ + tid];
            idxA[tid] = ia;
            padf[tid] = (ia == LQ - 1) ? 1.f : 0.f;
        } else if (tid < 2 * MQ) {
            idxB[tid - MQ] = bdeg[atom * MQ + tid - MQ];
        }
        __syncthreads();
        for (int i = tid; i < AD + MQ * CD; i += 256) {
            if (i < AD) {
                atomrow[i] = atom_list[atom * AD + i];
            } else {
                int j = i - AD;
                int m = j / CD, c = j % CD;
                float v;
                if (c < AD) v = atom_list[(bmol * LQ + idxA[m]) * AD + c];
                else        v = bond_list[(bmol * LQ + idxB[m]) * BD + (c - AD)];
                acts[m * 52 + c] = v;
            }
        }
        __syncthreads();

        float af = ba;
        #pragma unroll
        for (int k = 0; k < AD; k++) af += Wa[k * FPD + f] * atomrow[k];
        af = leakyf(af);

        float nf[MQ];
        #pragma unroll
        for (int m = 0; m < MQ; m++) nf[m] = bn;
        #pragma unroll 7
        for (int k = 0; k < CD; k++) {
            float w = Wn[k * FPD + f];
            #pragma unroll
            for (int m = 0; m < MQ; m++) nf[m] += w * acts[m * 52 + k];
        }
        #pragma unroll
        for (int m = 0; m < MQ; m++) nf[m] = leakyf(nf[m]);

        float v[7];
        v[0] = af * wal1;
        #pragma unroll
        for (int m = 0; m < MQ; m++) v[1 + m] = nf[m] * wal2;
        #pragma unroll
        for (int off = 16; off > 0; off >>= 1) {
            #pragma unroll
            for (int j = 0; j < 7; j++)
                v[j] += __shfl_down_sync(0xffffffffu, v[j], off);
        }
        if (lane == 0) {
            #pragma unroll
            for (int j = 0; j < 7; j++) red[warp * 7 + j] = v[j];
        }
        __syncthreads();

        float sums[7];
        #pragma unroll
        for (int j = 0; j < 7; j++) {
            float s = 0.f;
            #pragma unroll
            for (int w = 0; w < 8; w++) s += red[w * 7 + j];
            sums[j] = s;
        }
        float sc[MQ], mx = -INFINITY;
        #pragma unroll
        for (int m = 0; m < MQ; m++) {
            float s = leakyf(sums[0] + sums[1 + m] + bal);
            if (padf[m] > 0.5f) s += -9e8f;
            sc[m] = s;
            mx = fmaxf(mx, s);
        }
        float e[MQ], se = 0.f;
        #pragma unroll
        for (int m = 0; m < MQ; m++) { e[m] = expf(sc[m] - mx); se += e[m]; }
        float inv = 1.f / se;
        float asum = 0.f, sf = 0.f;
        #pragma unroll
        for (int m = 0; m < MQ; m++) {
            float a = e[m] * inv;
            if (padf[m] > 0.5f) a = 0.f;
            asum += a;
            sf += a * nf[m];
        }
        const int o = atom * FPD + f;
        g_af[o] = af;
        split2(af, g_af_hi[o], g_af_lo[o]);
        split2(sf, g_s_hi[o],  g_s_lo[o]);
        if (tid == 0) g_asum[atom] = asum;
    }
}

// ---------------------------------------------------------------------------
// Kernel 2a: ctx = elu( s @ W_att^T + asum*b ) via mma.sync bf16 hi/lo (3-pass)
// CTA: M=128 x N=64, 8 warps (4x2), warp 32x32, KC=32, cp.async double-buffer.
// ---------------------------------------------------------------------------
#define CTX_AH 0
#define CTX_AL 10240
#define CTX_BH 20480
#define CTX_BL 25600
#define CTX_BUF 30720
#define CTX_BATT (2 * CTX_BUF)
#define CTX_SMEM (CTX_BATT + 256)

__global__ void __launch_bounds__(256) ctx_mma(const float* __restrict__ batt_g)
{
    extern __shared__ char sm[];
    const uint32_t sb = s2u(sm);
    float* sbatt = (float*)(sm + CTX_BATT);
    const int tid = threadIdx.x, wid = tid >> 5, lane = tid & 31;
    const int m0 = blockIdx.x * 128, n0 = blockIdx.y * 64;
    const int Moff = (wid & 3) * 32, Noff = (wid >> 2) * 32;

    if (tid < 64) sbatt[tid] = batt_g[n0 + tid];

    const int r_ = tid >> 2, q_ = tid & 3;
    const uint32_t soff = (uint32_t)(r_ * 80 + q_ * 16);
    const int aoff0 = (m0 + r_) * FPD + q_ * 8;
    const int aoff1 = (m0 + 64 + r_) * FPD + q_ * 8;
    const int boff  = (n0 + r_) * FPD + q_ * 8;

    const int row0 = lane >> 2, qb = lane & 3;
    float acc[2][4][4] = {};

    // prologue: stage chunk 0
    cpa16(sb + CTX_AH + soff,        g_s_hi + aoff0);
    cpa16(sb + CTX_AH + 5120 + soff, g_s_hi + aoff1);
    cpa16(sb + CTX_AL + soff,        g_s_lo + aoff0);
    cpa16(sb + CTX_AL + 5120 + soff, g_s_lo + aoff1);
    cpa16(sb + CTX_BH + soff, g_Wat_h + boff);
    cpa16(sb + CTX_BL + soff, g_Wat_l + boff);
    CP_COMMIT();

    for (int c = 0; c < 8; c++) {
        if (c < 7) {
            const int k0 = (c + 1) * 32;
            const uint32_t bo = ((c + 1) & 1) * CTX_BUF;
            cpa16(sb + bo + CTX_AH + soff,        g_s_hi + aoff0 + k0);
            cpa16(sb + bo + CTX_AH + 5120 + soff, g_s_hi + aoff1 + k0);
            cpa16(sb + bo + CTX_AL + soff,        g_s_lo + aoff0 + k0);
            cpa16(sb + bo + CTX_AL + 5120 + soff, g_s_lo + aoff1 + k0);
            cpa16(sb + bo + CTX_BH + soff, g_Wat_h + boff + k0);
            cpa16(sb + bo + CTX_BL + soff, g_Wat_l + boff + k0);
            CP_COMMIT();
            CP_WAIT1();
        } else {
            CP_WAIT0();
        }
        __syncthreads();
        const char* bb = sm + (c & 1) * CTX_BUF;
        const uint32_t* wAh = (const uint32_t*)(bb + CTX_AH);
        const uint32_t* wAl = (const uint32_t*)(bb + CTX_AL);
        const uint32_t* wBh = (const uint32_t*)(bb + CTX_BH);
        const uint32_t* wBl = (const uint32_t*)(bb + CTX_BL);
        #pragma unroll
        for (int ks = 0; ks < 2; ks++) {
            const int q = qb + ks * 8;
            uint32_t ah[2][4], al[2][4];
            #pragma unroll
            for (int mt = 0; mt < 2; mt++) {
                int rr = Moff + mt * 16 + row0;
                ldA(ah[mt], wAh, rr, q);
                ldA(al[mt], wAl, rr, q);
            }
            #pragma unroll
            for (int nt = 0; nt < 4; nt++) {
                int nn = Noff + nt * 8 + row0;
                uint32_t bh2[2], bl2[2];
                ldB(bh2, wBh, nn, q);
                ldB(bl2, wBl, nn, q);
                #pragma unroll
                for (int mt = 0; mt < 2; mt++) {
                    mma16816(acc[mt][nt], ah[mt], bh2);
                    mma16816(acc[mt][nt], ah[mt], bl2);
                    mma16816(acc[mt][nt], al[mt], bh2);
                }
            }
        }
        __syncthreads();
    }

    // epilogue: + asum*b, elu, split to bf16 hi/lo
    #pragma unroll
    for (int mt = 0; mt < 2; mt++) {
        int r0 = m0 + Moff + mt * 16 + row0;
        float as0 = g_asum[r0], as1 = g_asum[r0 + 8];
        #pragma unroll
        for (int nt = 0; nt < 4; nt++) {
            int cl = Noff + nt * 8 + qb * 2;
            int col = n0 + cl;
            float b0 = sbatt[cl], b1 = sbatt[cl + 1];
            float t00 = acc[mt][nt][0] + as0 * b0, t01 = acc[mt][nt][1] + as0 * b1;
            float t10 = acc[mt][nt][2] + as1 * b0, t11 = acc[mt][nt][3] + as1 * b1;
            t00 = t00 > 0.f ? t00 : expm1f(t00);
            t01 = t01 > 0.f ? t01 : expm1f(t01);
            t10 = t10 > 0.f ? t10 : expm1f(t10);
            t11 = t11 > 0.f ? t11 : expm1f(t11);
            __nv_bfloat16 h0, l0, h1, l1;
            split2(t00, h0, l0); split2(t01, h1, l1);
            *(uint32_t*)&g_cx_hi[r0 * FPD + col] = pk2(h0, h1);
            *(uint32_t*)&g_cx_lo[r0 * FPD + col] = pk2(l0, l1);
            split2(t10, h0, l0); split2(t11, h1, l1);
            *(uint32_t*)&g_cx_hi[(r0 + 8) * FPD + col] = pk2(h0, h1);
            *(uint32_t*)&g_cx_lo[(r0 + 8) * FPD + col] = pk2(l0, l1);
        }
    }
}

// ---------------------------------------------------------------------------
// Kernel 2b: GRU via mma.sync — 6 gate accumulators in registers + fused epi.
// CTA: M=64 x N=64, 8 warps (2x4), warp 32x16 per gate, KC=32, double-buffer.
// ---------------------------------------------------------------------------
#define GB_TILE 5120
#define GB_B    (4 * GB_TILE)        // B tiles start (tile idx 4..15)
#define GB_BUF  (16 * GB_TILE)       // 81920
#define GB_BIAS (2 * GB_BUF)         // 163840: float[384]
#define GB_SMEM (GB_BIAS + 1536)

__global__ void __launch_bounds__(256) gru_mma(
    const float* __restrict__ b_ih, const float* __restrict__ b_hh,
    float* __restrict__ out)
{
    extern __shared__ char sm[];
    const uint32_t sb = s2u(sm);
    float* sbias = (float*)(sm + GB_BIAS);
    const int tid = threadIdx.x, wid = tid >> 5, lane = tid & 31;
    const int m0 = blockIdx.x * 64, f0 = blockIdx.y * 64;
    const int Moff = (wid & 1) * 32, Noff = (wid >> 1) * 16;

    // FIX (R4 bug): 384 bias values, 256 threads -> strided loop, not `if (tid<384)`
    for (int i = tid; i < 384; i += 256) {
        int g = i >> 6, fl = i & 63;
        sbias[i] = (g < 3) ? b_ih[g * FPD + f0 + fl] : b_hh[(g - 3) * FPD + f0 + fl];
    }

    const int r_ = tid >> 2, q_ = tid & 3;
    const uint32_t soff = (uint32_t)(r_ * 80 + q_ * 16);
    const int aoff = (m0 + r_) * FPD + q_ * 8;
    const int woff0 = (0 * FPD + f0 + r_) * FPD + q_ * 8;
    const int woff1 = (1 * FPD + f0 + r_) * FPD + q_ * 8;
    const int woff2 = (2 * FPD + f0 + r_) * FPD + q_ * 8;

    const int row0 = lane >> 2, qb = lane & 3;
    float acc[6][2][2][4] = {};

    // prologue: stage chunk 0
    {
        const uint32_t b0_ = sb;
        cpa16(b0_ + 0 * GB_TILE + soff, g_cx_hi + aoff);
        cpa16(b0_ + 1 * GB_TILE + soff, g_cx_lo + aoff);
        cpa16(b0_ + 2 * GB_TILE + soff, g_af_hi + aoff);
        cpa16(b0_ + 3 * GB_TILE + soff, g_af_lo + aoff);
        cpa16(b0_ + GB_B + 0 * GB_TILE + soff,  g_Wih_h + woff0);
        cpa16(b0_ + GB_B + 1 * GB_TILE + soff,  g_Wih_l + woff0);
        cpa16(b0_ + GB_B + 2 * GB_TILE + soff,  g_Wih_h + woff1);
        cpa16(b0_ + GB_B + 3 * GB_TILE + soff,  g_Wih_l + woff1);
        cpa16(b0_ + GB_B + 4 * GB_TILE + soff,  g_Wih_h + woff2);
        cpa16(b0_ + GB_B + 5 * GB_TILE + soff,  g_Wih_l + woff2);
        cpa16(b0_ + GB_B + 6 * GB_TILE + soff,  g_Whh_h + woff0);
        cpa16(b0_ + GB_B + 7 * GB_TILE + soff,  g_Whh_l + woff0);
        cpa16(b0_ + GB_B + 8 * GB_TILE + soff,  g_Whh_h + woff1);
        cpa16(b0_ + GB_B + 9 * GB_TILE + soff,  g_Whh_l + woff1);
        cpa16(b0_ + GB_B + 10 * GB_TILE + soff, g_Whh_h + woff2);
        cpa16(b0_ + GB_B + 11 * GB_TILE + soff, g_Whh_l + woff2);
        CP_COMMIT();
    }

    for (int c = 0; c < 8; c++) {
        if (c < 7) {
            const int k0 = (c + 1) * 32;
            const uint32_t bs = sb + ((c + 1) & 1) * GB_BUF;
            cpa16(bs + 0 * GB_TILE + soff, g_cx_hi + aoff + k0);
            cpa16(bs + 1 * GB_TILE + soff, g_cx_lo + aoff + k0);
            cpa16(bs + 2 * GB_TILE + soff, g_af_hi + aoff + k0);
            cpa16(bs + 3 * GB_TILE + soff, g_af_lo + aoff + k0);
            cpa16(bs + GB_B + 0 * GB_TILE + soff,  g_Wih_h + woff0 + k0);
            cpa16(bs + GB_B + 1 * GB_TILE + soff,  g_Wih_l + woff0 + k0);
            cpa16(bs + GB_B + 2 * GB_TILE + soff,  g_Wih_h + woff1 + k0);
            cpa16(bs + GB_B + 3 * GB_TILE + soff,  g_Wih_l + woff1 + k0);
            cpa16(bs + GB_B + 4 * GB_TILE + soff,  g_Wih_h + woff2 + k0);
            cpa16(bs + GB_B + 5 * GB_TILE + soff,  g_Wih_l + woff2 + k0);
            cpa16(bs + GB_B + 6 * GB_TILE + soff,  g_Whh_h + woff0 + k0);
            cpa16(bs + GB_B + 7 * GB_TILE + soff,  g_Whh_l + woff0 + k0);
            cpa16(bs + GB_B + 8 * GB_TILE + soff,  g_Whh_h + woff1 + k0);
            cpa16(bs + GB_B + 9 * GB_TILE + soff,  g_Whh_l + woff1 + k0);
            cpa16(bs + GB_B + 10 * GB_TILE + soff, g_Whh_h + woff2 + k0);
            cpa16(bs + GB_B + 11 * GB_TILE + soff, g_Whh_l + woff2 + k0);
            CP_COMMIT();
            CP_WAIT1();
        } else {
            CP_WAIT0();
        }
        __syncthreads();
        const char* bb = sm + (c & 1) * GB_BUF;
        #pragma unroll
        for (int ks = 0; ks < 2; ks++) {
            const int q = qb + ks * 8;
            uint32_t Ah[2][2][4], Al[2][2][4];   // [am: 0=ctx 1=af][mt]
            #pragma unroll
            for (int am = 0; am < 2; am++) {
                const uint32_t* wh = (const uint32_t*)(bb + (am * 2) * GB_TILE);
                const uint32_t* wl = (const uint32_t*)(bb + (am * 2 + 1) * GB_TILE);
                #pragma unroll
                for (int mt = 0; mt < 2; mt++) {
                    int rr = Moff + mt * 16 + row0;
                    ldA(Ah[am][mt], wh, rr, q);
                    ldA(Al[am][mt], wl, rr, q);
                }
            }
            #pragma unroll
            for (int g = 0; g < 6; g++) {
                const uint32_t* wbh = (const uint32_t*)(bb + GB_B + (g * 2) * GB_TILE);
                const uint32_t* wbl = (const uint32_t*)(bb + GB_B + (g * 2 + 1) * GB_TILE);
                const int am = (g < 3) ? 0 : 1;
                #pragma unroll
                for (int nt = 0; nt < 2; nt++) {
                    int nn = Noff + nt * 8 + row0;
                    uint32_t bh2[2], bl2[2];
                    ldB(bh2, wbh, nn, q);
                    ldB(bl2, wbl, nn, q);
                    #pragma unroll
                    for (int mt = 0; mt < 2; mt++) {
                        mma16816(acc[g][mt][nt], Ah[am][mt], bh2);
                        mma16816(acc[g][mt][nt], Ah[am][mt], bl2);
                        mma16816(acc[g][mt][nt], Al[am][mt], bh2);
                    }
                }
            }
        }
        __syncthreads();
    }

    // fused GRU + ReLU epilogue  (gate tile order: 0=i_r 1=i_z 2=i_n 3=h_r 4=h_z 5=h_n)
    #pragma unroll
    for (int mt = 0; mt < 2; mt++)
        #pragma unroll
        for (int rp = 0; rp < 2; rp++) {
            int row = m0 + Moff + mt * 16 + row0 + rp * 8;
            #pragma unroll
            for (int nt = 0; nt < 2; nt++) {
                int cl = Noff + nt * 8 + qb * 2;
                int colG = f0 + cl;
                float o2[2];
                #pragma unroll
                for (int j = 0; j < 2; j++) {
                    int ci = rp * 2 + j;
                    float ir  = acc[0][mt][nt][ci] + sbias[cl + j];
                    float iz  = acc[1][mt][nt][ci] + sbias[64 + cl + j];
                    float in_ = acc[2][mt][nt][ci] + sbias[128 + cl + j];
                    float hr  = acc[3][mt][nt][ci] + sbias[192 + cl + j];
                    float hz  = acc[4][mt][nt][ci] + sbias[256 + cl + j];
                    float hn  = acc[5][mt][nt][ci] + sbias[320 + cl + j];
                    float r = sigmf(ir + hr), z = sigmf(iz + hz);
                    float n = tanhf(in_ + r * hn);
                    float h = g_af[row * FPD + colG + j];
                    o2[j] = fmaxf((1.f - z) * n + z * h, 0.f);
                }
                *(float2*)&out[row * FPD + colG] = make_float2(o2[0], o2[1]);
            }
        }
}

// ---------------------------------------------------------------------------
// Launcher
// ---------------------------------------------------------------------------
extern "C" void kernel_launch(void* const* d_in, const int* in_sizes, int n_in,
                              void* d_out, int out_size)
{
    const float* atom_list = (const float*)d_in[0];
    const float* bond_list = (const float*)d_in[1];
    const int*   adeg      = (const int*)  d_in[2];
    const int*   bdeg      = (const int*)  d_in[3];
    const float* W_atom   = (const float*)d_in[5];
    const float* b_atom   = (const float*)d_in[6];
    const float* W_nbr    = (const float*)d_in[7];
    const float* b_nbr    = (const float*)d_in[8];
    const float* W_align  = (const float*)d_in[9];
    const float* b_align  = (const float*)d_in[10];
    const float* W_attend = (const float*)d_in[11];
    const float* b_attend = (const float*)d_in[12];
    const float* W_ih     = (const float*)d_in[13];
    const float* b_ih     = (const float*)d_in[14];
    const float* W_hh     = (const float*)d_in[15];
    const float* b_hh     = (const float*)d_in[16];
    float* out = (float*)d_out;
    (void)in_sizes; (void)n_in; (void)out_size;

    cudaFuncSetAttribute(attn_kernel, cudaFuncAttributeMaxDynamicSharedMemorySize, K1_SMEM);
    cudaFuncSetAttribute(ctx_mma,     cudaFuncAttributeMaxDynamicSharedMemorySize, CTX_SMEM);
    cudaFuncSetAttribute(gru_mma,     cudaFuncAttributeMaxDynamicSharedMemorySize, GB_SMEM);

    prep_w<<<(3 * FPD * FPD + 255) / 256, 256>>>(W_attend, W_ih, W_hh);

    attn_kernel<<<NATOMS / K1_ATOMS, 256, K1_SMEM>>>(
        atom_list, bond_list, adeg, bdeg,
        W_atom, b_atom, W_nbr, b_nbr, W_align, b_align);

    dim3 gc(NATOMS / 128, FPD / 64);
    ctx_mma<<<gc, 256, CTX_SMEM>>>(b_attend);

    dim3 gg(NATOMS / 64, FPD / 64);
    gru_mma<<<gg, 256, GB_SMEM>>>(b_ih, b_hh, out);
}

// round 6
// speedup vs baseline: 1.6514x; 1.1199x over previous
#include <cuda_runtime.h>
#include <cuda_bf16.h>
#include <math.h>
#include <stdint.h>

// Problem constants
#define BQ   512
#define LQ   128
#define MQ   6
#define AD   39
#define BD   10
#define CD   49
#define FPD  256
#define NATOMS (BQ * LQ)   // 65536

// ---------------------------------------------------------------------------
// Device-global scratch (allocation-free rule)
// ---------------------------------------------------------------------------
__device__ __align__(16) float g_af[NATOMS * FPD];
__device__ __align__(16) float g_asum[NATOMS];
__device__ __align__(16) __nv_bfloat16 g_s_hi[NATOMS * FPD],  g_s_lo[NATOMS * FPD];
__device__ __align__(16) __nv_bfloat16 g_af_hi[NATOMS * FPD], g_af_lo[NATOMS * FPD];
__device__ __align__(16) __nv_bfloat16 g_cx_hi[NATOMS * FPD], g_cx_lo[NATOMS * FPD];
__device__ __align__(16) __nv_bfloat16 g_Wat_h[FPD * FPD],     g_Wat_l[FPD * FPD];
__device__ __align__(16) __nv_bfloat16 g_Wih_h[3 * FPD * FPD], g_Wih_l[3 * FPD * FPD];
__device__ __align__(16) __nv_bfloat16 g_Whh_h[3 * FPD * FPD], g_Whh_l[3 * FPD * FPD];

// ---------------------------------------------------------------------------
// Helpers
// ---------------------------------------------------------------------------
__device__ __forceinline__ uint32_t s2u(const void* p) {
    uint32_t a;
    asm("{ .reg .u64 t; cvta.to.shared.u64 t, %1; cvt.u32.u64 %0, t; }" : "=r"(a) : "l"(p));
    return a;
}
__device__ __forceinline__ void mma16816(float* c, const uint32_t* a, const uint32_t* b) {
    asm volatile("mma.sync.aligned.m16n8k16.row.col.f32.bf16.bf16.f32 "
        "{%0,%1,%2,%3}, {%4,%5,%6,%7}, {%8,%9}, {%0,%1,%2,%3};"
        : "+f"(c[0]), "+f"(c[1]), "+f"(c[2]), "+f"(c[3])
        : "r"(a[0]), "r"(a[1]), "r"(a[2]), "r"(a[3]), "r"(b[0]), "r"(b[1]));
}
// ldmatrix x4: lanes 0-7 matrix0 rows, 8-15 m1, 16-23 m2, 24-31 m3; regs r0..r3 <- m0..m3
__device__ __forceinline__ void ldm4(uint32_t* r, uint32_t addr) {
    asm volatile("ldmatrix.sync.aligned.m8n8.x4.shared.b16 {%0,%1,%2,%3}, [%4];"
        : "=r"(r[0]), "=r"(r[1]), "=r"(r[2]), "=r"(r[3]) : "r"(addr));
}
__device__ __forceinline__ void cpa16(uint32_t d, const void* s) {
    asm volatile("cp.async.cg.shared.global [%0], [%1], 16;" :: "r"(d), "l"(s) : "memory");
}
#define CP_COMMIT() asm volatile("cp.async.commit_group;" ::: "memory")
#define CP_WAIT1()  asm volatile("cp.async.wait_group 1;" ::: "memory")
#define CP_WAIT0()  asm volatile("cp.async.wait_group 0;" ::: "memory")

__device__ __forceinline__ float leakyf(float x) { return x > 0.f ? x : 0.01f * x; }
__device__ __forceinline__ float sigmf(float x)  { return 1.f / (1.f + expf(-x)); }
__device__ __forceinline__ void split2(float v, __nv_bfloat16& h, __nv_bfloat16& l) {
    h = __float2bfloat16(v);
    l = __float2bfloat16(v - __bfloat162float(h));
}
__device__ __forceinline__ uint32_t pk2(__nv_bfloat16 a, __nv_bfloat16 b) {
    return (uint32_t)__bfloat16_as_ushort(a) | ((uint32_t)__bfloat16_as_ushort(b) << 16);
}

// ---------------------------------------------------------------------------
// Kernel 0: split weights to bf16 hi/lo pairs
// ---------------------------------------------------------------------------
__global__ void prep_w(const float* __restrict__ Wat, const float* __restrict__ Wih,
                       const float* __restrict__ Whh) {
    int i = blockIdx.x * 256 + threadIdx.x;
    if (i < FPD * FPD)     split2(Wat[i], g_Wat_h[i], g_Wat_l[i]);
    if (i < 3 * FPD * FPD) {
        split2(Wih[i], g_Wih_h[i], g_Wih_l[i]);
        split2(Whh[i], g_Whh_h[i], g_Whh_l[i]);
    }
}

// ---------------------------------------------------------------------------
// Kernel 1: fused gather + projections + attention (2 atoms / iter, float4)
// ---------------------------------------------------------------------------
#define K1_ATOMS 32
#define O_WA   0
#define O_WN   (AD * FPD)                 // 9984
#define O_WAL  (O_WN + CD * FPD)          // 22528
#define O_ACTS (O_WAL + 2 * FPD)          // 23040  [12][56]
#define O_AROW (O_ACTS + 12 * 56)         // 23712  [2][40]
#define O_RED  (O_AROW + 80)              // 23792  [8][14]
#define O_PADF (O_RED + 112)              // 23904  [12]
#define O_IDX  (O_PADF + 12)              // 23916  [24] ints
#define K1_SMEM ((O_IDX + 24) * 4)

__global__ void __launch_bounds__(256, 2) attn_kernel(
    const float* __restrict__ atom_list, const float* __restrict__ bond_list,
    const int*   __restrict__ adeg,      const int*   __restrict__ bdeg,
    const float* __restrict__ W_atom,    const float* __restrict__ b_atom,
    const float* __restrict__ W_nbr,     const float* __restrict__ b_nbr,
    const float* __restrict__ W_align,   const float* __restrict__ b_align)
{
    extern __shared__ float smem[];
    float* Wa   = smem + O_WA;
    float* Wn   = smem + O_WN;
    float* wal  = smem + O_WAL;
    float* acts = smem + O_ACTS;
    float* arow = smem + O_AROW;
    float* red  = smem + O_RED;
    float* padf = smem + O_PADF;
    int*   idx  = (int*)(smem + O_IDX);

    const int tid = threadIdx.x;
    const int f   = tid;

    for (int i = tid; i < AD * FPD; i += 256) {
        int ff = i / AD, k = i % AD;
        Wa[k * FPD + ff] = W_atom[i];
    }
    for (int i = tid; i < CD * FPD; i += 256) {
        int ff = i / CD, k = i % CD;
        Wn[k * FPD + ff] = W_nbr[i];
    }
    for (int i = tid; i < 2 * FPD; i += 256) wal[i] = W_align[i];

    const float ba  = b_atom[f];
    const float bn  = b_nbr[f];
    const float bal = b_align[0];
    __syncthreads();

    const float wal1 = wal[f];
    const float wal2 = wal[FPD + f];
    const int   warp = tid >> 5;
    const int   lane = tid & 31;
    const int   base = blockIdx.x * K1_ATOMS;

    for (int ai = 0; ai < K1_ATOMS; ai += 2) {
        const int atom0 = base + ai;
        const int bmol  = atom0 / LQ;   // both atoms in one molecule (128 % 32 == 0)

        __syncthreads();
        if (tid < 24) {
            int a = tid / 12, j = tid % 12;
            int atom = atom0 + a;
            if (j < MQ) {
                int ia = adeg[atom * MQ + j];
                idx[a * 12 + j] = ia;
                padf[a * 6 + j] = (ia == LQ - 1) ? 1.f : 0.f;
            } else {
                idx[a * 12 + j] = bdeg[atom * MQ + (j - MQ)];
            }
        }
        __syncthreads();
        for (int i = tid; i < 2 * (AD + MQ * CD); i += 256) {
            int a = i / 333, j = i % 333;
            if (j < AD) {
                arow[a * 40 + j] = atom_list[(atom0 + a) * AD + j];
            } else {
                int m = (j - AD) / CD, c = (j - AD) % CD;
                float v;
                if (c < AD) v = atom_list[(bmol * LQ + idx[a * 12 + m]) * AD + c];
                else        v = bond_list[(bmol * LQ + idx[a * 12 + 6 + m]) * BD + (c - AD)];
                acts[(a * 6 + m) * 56 + c] = v;
            }
        }
        __syncthreads();

        // projections
        float af[2]; af[0] = ba; af[1] = ba;
        #pragma unroll
        for (int k0 = 0; k0 < 36; k0 += 4) {
            float w0 = Wa[(k0 + 0) * FPD + f], w1 = Wa[(k0 + 1) * FPD + f];
            float w2 = Wa[(k0 + 2) * FPD + f], w3 = Wa[(k0 + 3) * FPD + f];
            #pragma unroll
            for (int a = 0; a < 2; a++) {
                float4 x = *(const float4*)&arow[a * 40 + k0];
                af[a] += w0 * x.x + w1 * x.y + w2 * x.z + w3 * x.w;
            }
        }
        {
            float w0 = Wa[36 * FPD + f], w1 = Wa[37 * FPD + f], w2 = Wa[38 * FPD + f];
            #pragma unroll
            for (int a = 0; a < 2; a++)
                af[a] += w0 * arow[a * 40 + 36] + w1 * arow[a * 40 + 37] + w2 * arow[a * 40 + 38];
        }
        af[0] = leakyf(af[0]); af[1] = leakyf(af[1]);

        float nf[2][MQ];
        #pragma unroll
        for (int a = 0; a < 2; a++)
            #pragma unroll
            for (int m = 0; m < MQ; m++) nf[a][m] = bn;
        #pragma unroll 4
        for (int k0 = 0; k0 < 48; k0 += 4) {
            float w0 = Wn[(k0 + 0) * FPD + f], w1 = Wn[(k0 + 1) * FPD + f];
            float w2 = Wn[(k0 + 2) * FPD + f], w3 = Wn[(k0 + 3) * FPD + f];
            #pragma unroll
            for (int a = 0; a < 2; a++)
                #pragma unroll
                for (int m = 0; m < MQ; m++) {
                    float4 x = *(const float4*)&acts[(a * 6 + m) * 56 + k0];
                    nf[a][m] += w0 * x.x + w1 * x.y + w2 * x.z + w3 * x.w;
                }
        }
        {
            float w = Wn[48 * FPD + f];
            #pragma unroll
            for (int a = 0; a < 2; a++)
                #pragma unroll
                for (int m = 0; m < MQ; m++)
                    nf[a][m] += w * acts[(a * 6 + m) * 56 + 48];
        }
        #pragma unroll
        for (int a = 0; a < 2; a++)
            #pragma unroll
            for (int m = 0; m < MQ; m++) nf[a][m] = leakyf(nf[a][m]);

        // cross-feature dot products
        float v[14];
        #pragma unroll
        for (int a = 0; a < 2; a++) {
            v[a * 7] = af[a] * wal1;
            #pragma unroll
            for (int m = 0; m < MQ; m++) v[a * 7 + 1 + m] = nf[a][m] * wal2;
        }
        #pragma unroll
        for (int off = 16; off > 0; off >>= 1)
            #pragma unroll
            for (int j = 0; j < 14; j++)
                v[j] += __shfl_down_sync(0xffffffffu, v[j], off);
        if (lane == 0)
            #pragma unroll
            for (int j = 0; j < 14; j++) red[warp * 14 + j] = v[j];
        __syncthreads();

        // softmax + outputs
        #pragma unroll
        for (int a = 0; a < 2; a++) {
            float sums[7];
            #pragma unroll
            for (int j = 0; j < 7; j++) {
                float s = 0.f;
                #pragma unroll
                for (int w = 0; w < 8; w++) s += red[w * 14 + a * 7 + j];
                sums[j] = s;
            }
            float sc[MQ], mx = -INFINITY;
            #pragma unroll
            for (int m = 0; m < MQ; m++) {
                float s = leakyf(sums[0] + sums[1 + m] + bal);
                if (padf[a * 6 + m] > 0.5f) s += -9e8f;
                sc[m] = s;
                mx = fmaxf(mx, s);
            }
            float e[MQ], se = 0.f;
            #pragma unroll
            for (int m = 0; m < MQ; m++) { e[m] = expf(sc[m] - mx); se += e[m]; }
            float inv = 1.f / se;
            float asum = 0.f, sf = 0.f;
            #pragma unroll
            for (int m = 0; m < MQ; m++) {
                float aw = e[m] * inv;
                if (padf[a * 6 + m] > 0.5f) aw = 0.f;
                asum += aw;
                sf   += aw * nf[a][m];
            }
            const int atom = atom0 + a;
            const int o = atom * FPD + f;
            g_af[o] = af[a];
            split2(af[a], g_af_hi[o], g_af_lo[o]);
            split2(sf,    g_s_hi[o],  g_s_lo[o]);
            if (tid == 0) g_asum[atom] = asum;
        }
    }
}

// ---------------------------------------------------------------------------
// Kernel 2a: ctx = elu( s @ W_att^T + asum*b ), mma.sync bf16 hi/lo, ldmatrix
// CTA: M=128 x N=64, 8 warps (4x2), warp 32x32, KC=32 (80B rows), dbl-buffer.
// ---------------------------------------------------------------------------
#define CTX_AH 0
#define CTX_AL 10240
#define CTX_BH 20480
#define CTX_BL 25600
#define CTX_BUF 30720
#define CTX_BATT (2 * CTX_BUF)
#define CTX_SMEM (CTX_BATT + 256)

__global__ void __launch_bounds__(256) ctx_mma(const float* __restrict__ batt_g)
{
    extern __shared__ char sm[];
    const uint32_t sb = s2u(sm);
    float* sbatt = (float*)(sm + CTX_BATT);
    const int tid = threadIdx.x, wid = tid >> 5, lane = tid & 31;
    const int m0 = blockIdx.x * 128, n0 = blockIdx.y * 64;
    const int Moff = (wid & 3) * 32, Noff = (wid >> 2) * 32;

    if (tid < 64) sbatt[tid] = batt_g[n0 + tid];

    const int r_ = tid >> 2, q_ = tid & 3;
    const uint32_t soff = (uint32_t)(r_ * 80 + q_ * 16);
    const int aoff0 = (m0 + r_) * FPD + q_ * 8;
    const int aoff1 = (m0 + 64 + r_) * FPD + q_ * 8;
    const int boff  = (n0 + r_) * FPD + q_ * 8;

    // ldmatrix lane-address offsets (80B row stride)
    const uint32_t a_lo = (uint32_t)((lane & 15) * 80 + (lane >> 4) * 16);
    const uint32_t b_lo = (uint32_t)(((lane & 7) + ((lane >> 4) << 3)) * 80 + ((lane >> 3) & 1) * 16);

    const int row0 = lane >> 2, qb = lane & 3;
    float acc[2][4][4] = {};

    cpa16(sb + CTX_AH + soff,        g_s_hi + aoff0);
    cpa16(sb + CTX_AH + 5120 + soff, g_s_hi + aoff1);
    cpa16(sb + CTX_AL + soff,        g_s_lo + aoff0);
    cpa16(sb + CTX_AL + 5120 + soff, g_s_lo + aoff1);
    cpa16(sb + CTX_BH + soff, g_Wat_h + boff);
    cpa16(sb + CTX_BL + soff, g_Wat_l + boff);
    CP_COMMIT();

    for (int c = 0; c < 8; c++) {
        if (c < 7) {
            const int k0 = (c + 1) * 32;
            const uint32_t bo = ((c + 1) & 1) * CTX_BUF;
            cpa16(sb + bo + CTX_AH + soff,        g_s_hi + aoff0 + k0);
            cpa16(sb + bo + CTX_AH + 5120 + soff, g_s_hi + aoff1 + k0);
            cpa16(sb + bo + CTX_AL + soff,        g_s_lo + aoff0 + k0);
            cpa16(sb + bo + CTX_AL + 5120 + soff, g_s_lo + aoff1 + k0);
            cpa16(sb + bo + CTX_BH + soff, g_Wat_h + boff + k0);
            cpa16(sb + bo + CTX_BL + soff, g_Wat_l + boff + k0);
            CP_COMMIT();
            CP_WAIT1();
        } else {
            CP_WAIT0();
        }
        __syncthreads();
        const uint32_t bb = sb + (c & 1) * CTX_BUF;
        #pragma unroll
        for (int ks = 0; ks < 2; ks++) {
            uint32_t ah[2][4], al[2][4];
            #pragma unroll
            for (int mt = 0; mt < 2; mt++) {
                uint32_t ao = (uint32_t)((Moff + mt * 16) * 80) + a_lo + ks * 32;
                ldm4(ah[mt], bb + CTX_AH + ao);
                ldm4(al[mt], bb + CTX_AL + ao);
            }
            uint32_t bh[2][4], bl[2][4];
            #pragma unroll
            for (int p = 0; p < 2; p++) {
                uint32_t bo2 = (uint32_t)((Noff + p * 16) * 80) + b_lo + ks * 32;
                ldm4(bh[p], bb + CTX_BH + bo2);
                ldm4(bl[p], bb + CTX_BL + bo2);
            }
            #pragma unroll
            for (int mt = 0; mt < 2; mt++)
                #pragma unroll
                for (int nt = 0; nt < 4; nt++) {
                    const uint32_t* Bh = &bh[nt >> 1][(nt & 1) * 2];
                    const uint32_t* Bl = &bl[nt >> 1][(nt & 1) * 2];
                    mma16816(acc[mt][nt], ah[mt], Bh);
                    mma16816(acc[mt][nt], ah[mt], Bl);
                    mma16816(acc[mt][nt], al[mt], Bh);
                }
        }
        __syncthreads();
    }

    #pragma unroll
    for (int mt = 0; mt < 2; mt++) {
        int r0 = m0 + Moff + mt * 16 + row0;
        float as0 = g_asum[r0], as1 = g_asum[r0 + 8];
        #pragma unroll
        for (int nt = 0; nt < 4; nt++) {
            int cl = Noff + nt * 8 + qb * 2;
            int col = n0 + cl;
            float b0 = sbatt[cl], b1 = sbatt[cl + 1];
            float t00 = acc[mt][nt][0] + as0 * b0, t01 = acc[mt][nt][1] + as0 * b1;
            float t10 = acc[mt][nt][2] + as1 * b0, t11 = acc[mt][nt][3] + as1 * b1;
            t00 = t00 > 0.f ? t00 : expm1f(t00);
            t01 = t01 > 0.f ? t01 : expm1f(t01);
            t10 = t10 > 0.f ? t10 : expm1f(t10);
            t11 = t11 > 0.f ? t11 : expm1f(t11);
            __nv_bfloat16 h0, l0, h1, l1;
            split2(t00, h0, l0); split2(t01, h1, l1);
            *(uint32_t*)&g_cx_hi[r0 * FPD + col] = pk2(h0, h1);
            *(uint32_t*)&g_cx_lo[r0 * FPD + col] = pk2(l0, l1);
            split2(t10, h0, l0); split2(t11, h1, l1);
            *(uint32_t*)&g_cx_hi[(r0 + 8) * FPD + col] = pk2(h0, h1);
            *(uint32_t*)&g_cx_lo[(r0 + 8) * FPD + col] = pk2(l0, l1);
        }
    }
}

// ---------------------------------------------------------------------------
// Kernel 2b: GRU via mma.sync + ldmatrix. KC=16 (48B rows) -> ~100KB smem,
// 2 CTAs/SM. CTA: M=64 x N=64, 8 warps (2x4), warp 32x16 per gate.
// Tiles: 0 cx_hi, 1 cx_lo, 2 af_hi, 3 af_lo, 4..15 = (gate, hi/lo).
// ---------------------------------------------------------------------------
#define GT      3072                 // 64 rows x 48B
#define GB_B    (4 * GT)
#define GB_BUF  (16 * GT)            // 49152
#define GB_BIAS (2 * GB_BUF)         // 98304
#define GB_SMEM (GB_BIAS + 1536)

__global__ void __launch_bounds__(256) gru_mma(
    const float* __restrict__ b_ih, const float* __restrict__ b_hh,
    float* __restrict__ out)
{
    extern __shared__ char sm[];
    const uint32_t sb = s2u(sm);
    float* sbias = (float*)(sm + GB_BIAS);
    const int tid = threadIdx.x, wid = tid >> 5, lane = tid & 31;
    const int m0 = blockIdx.x * 64, f0 = blockIdx.y * 64;
    const int Moff = (wid & 1) * 32, Noff = (wid >> 1) * 16;

    for (int i = tid; i < 384; i += 256) {
        int g = i >> 6, fl = i & 63;
        sbias[i] = (g < 3) ? b_ih[g * FPD + f0 + fl] : b_hh[(g - 3) * FPD + f0 + fl];
    }

    // staging: thread covers (half, r_, part): 8 tile-pairs x 64 rows x 2 segs
    const int half = tid >> 7;           // selects hi(0)/lo(1) member of each pair
    const int r_   = (tid & 127) >> 1;   // row 0..63
    const int part = tid & 1;            // 16B segment within 32B row data
    const uint32_t soff = (uint32_t)(r_ * 48 + part * 16);
    const int aoff  = (m0 + r_) * FPD + part * 8;
    const int wrow0 = (0 * FPD + f0 + r_) * FPD + part * 8;
    const int wrow1 = (1 * FPD + f0 + r_) * FPD + part * 8;
    const int wrow2 = (2 * FPD + f0 + r_) * FPD + part * 8;

    // pair sources: hi member, lo member, row offset
    const __nv_bfloat16* srcH[8] = { g_cx_hi, g_af_hi, g_Wih_h, g_Wih_h, g_Wih_h,
                                     g_Whh_h, g_Whh_h, g_Whh_h };
    const __nv_bfloat16* srcL[8] = { g_cx_lo, g_af_lo, g_Wih_l, g_Wih_l, g_Wih_l,
                                     g_Whh_l, g_Whh_l, g_Whh_l };
    const int prow[8] = { aoff, aoff, wrow0, wrow1, wrow2, wrow0, wrow1, wrow2 };

    // ldmatrix lane-address offsets (48B row stride)
    const uint32_t a_lo = (uint32_t)((lane & 15) * 48 + (lane >> 4) * 16);
    const uint32_t b_lo = (uint32_t)(((lane & 7) + ((lane >> 4) << 3)) * 48 + ((lane >> 3) & 1) * 16);

    const int row0 = lane >> 2, qb = lane & 3;
    float acc[6][2][2][4] = {};

    // prologue: stage chunk 0
    #pragma unroll
    for (int j = 0; j < 8; j++) {
        const __nv_bfloat16* p = half ? srcL[j] : srcH[j];
        cpa16(sb + (uint32_t)((2 * j + half) * GT) + soff, p + prow[j]);
    }
    CP_COMMIT();

    for (int c = 0; c < 16; c++) {
        if (c < 15) {
            const int k0 = (c + 1) * 16;
            const uint32_t bs = sb + ((c + 1) & 1) * GB_BUF;
            #pragma unroll
            for (int j = 0; j < 8; j++) {
                const __nv_bfloat16* p = half ? srcL[j] : srcH[j];
                cpa16(bs + (uint32_t)((2 * j + half) * GT) + soff, p + prow[j] + k0);
            }
            CP_COMMIT();
            CP_WAIT1();
        } else {
            CP_WAIT0();
        }
        __syncthreads();
        const uint32_t bb = sb + (c & 1) * GB_BUF;

        uint32_t Ah[2][2][4], Al[2][2][4];   // [am: 0=ctx 1=af][mt]
        #pragma unroll
        for (int am = 0; am < 2; am++) {
            #pragma unroll
            for (int mt = 0; mt < 2; mt++) {
                uint32_t ao = (uint32_t)((Moff + mt * 16) * 48) + a_lo;
                ldm4(Ah[am][mt], bb + (uint32_t)((am * 2) * GT) + ao);
                ldm4(Al[am][mt], bb + (uint32_t)((am * 2 + 1) * GT) + ao);
            }
        }
        #pragma unroll
        for (int g = 0; g < 6; g++) {
            uint32_t bhf[4], blf[4];
            uint32_t bo2 = (uint32_t)(Noff * 48) + b_lo;
            ldm4(bhf, bb + GB_B + (uint32_t)((g * 2) * GT) + bo2);
            ldm4(blf, bb + GB_B + (uint32_t)((g * 2 + 1) * GT) + bo2);
            const int am = (g < 3) ? 0 : 1;
            #pragma unroll
            for (int nt = 0; nt < 2; nt++) {
                const uint32_t* Bh = &bhf[nt * 2];
                const uint32_t* Bl = &blf[nt * 2];
                #pragma unroll
                for (int mt = 0; mt < 2; mt++) {
                    mma16816(acc[g][mt][nt], Ah[am][mt], Bh);
                    mma16816(acc[g][mt][nt], Ah[am][mt], Bl);
                    mma16816(acc[g][mt][nt], Al[am][mt], Bh);
                }
            }
        }
        __syncthreads();
    }

    // fused GRU + ReLU epilogue (0=i_r 1=i_z 2=i_n 3=h_r 4=h_z 5=h_n)
    #pragma unroll
    for (int mt = 0; mt < 2; mt++)
        #pragma unroll
        for (int rp = 0; rp < 2; rp++) {
            int row = m0 + Moff + mt * 16 + row0 + rp * 8;
            #pragma unroll
            for (int nt = 0; nt < 2; nt++) {
                int cl = Noff + nt * 8 + qb * 2;
                int colG = f0 + cl;
                float o2[2];
                #pragma unroll
                for (int j = 0; j < 2; j++) {
                    int ci = rp * 2 + j;
                    float ir  = acc[0][mt][nt][ci] + sbias[cl + j];
                    float iz  = acc[1][mt][nt][ci] + sbias[64 + cl + j];
                    float in_ = acc[2][mt][nt][ci] + sbias[128 + cl + j];
                    float hr  = acc[3][mt][nt][ci] + sbias[192 + cl + j];
                    float hz  = acc[4][mt][nt][ci] + sbias[256 + cl + j];
                    float hn  = acc[5][mt][nt][ci] + sbias[320 + cl + j];
                    float r = sigmf(ir + hr), z = sigmf(iz + hz);
                    float n = tanhf(in_ + r * hn);
                    float h = g_af[row * FPD + colG + j];
                    o2[j] = fmaxf((1.f - z) * n + z * h, 0.f);
                }
                *(float2*)&out[row * FPD + colG] = make_float2(o2[0], o2[1]);
            }
        }
}

// ---------------------------------------------------------------------------
// Launcher
// ---------------------------------------------------------------------------
extern "C" void kernel_launch(void* const* d_in, const int* in_sizes, int n_in,
                              void* d_out, int out_size)
{
    const float* atom_list = (const float*)d_in[0];
    const float* bond_list = (const float*)d_in[1];
    const int*   adeg      = (const int*)  d_in[2];
    const int*   bdeg      = (const int*)  d_in[3];
    const float* W_atom   = (const float*)d_in[5];
    const float* b_atom   = (const float*)d_in[6];
    const float* W_nbr    = (const float*)d_in[7];
    const float* b_nbr    = (const float*)d_in[8];
    const float* W_align  = (const float*)d_in[9];
    const float* b_align  = (const float*)d_in[10];
    const float* W_attend = (const float*)d_in[11];
    const float* b_attend = (const float*)d_in[12];
    const float* W_ih     = (const float*)d_in[13];
    const float* b_ih     = (const float*)d_in[14];
    const float* W_hh     = (const float*)d_in[15];
    const float* b_hh     = (const float*)d_in[16];
    float* out = (float*)d_out;
    (void)in_sizes; (void)n_in; (void)out_size;

    cudaFuncSetAttribute(attn_kernel, cudaFuncAttributeMaxDynamicSharedMemorySize, K1_SMEM);
    cudaFuncSetAttribute(ctx_mma,     cudaFuncAttributeMaxDynamicSharedMemorySize, CTX_SMEM);
    cudaFuncSetAttribute(gru_mma,     cudaFuncAttributeMaxDynamicSharedMemorySize, GB_SMEM);

    prep_w<<<(3 * FPD * FPD + 255) / 256, 256>>>(W_attend, W_ih, W_hh);

    attn_kernel<<<NATOMS / K1_ATOMS, 256, K1_SMEM>>>(
        atom_list, bond_list, adeg, bdeg,
        W_atom, b_atom, W_nbr, b_nbr, W_align, b_align);

    dim3 gc(NATOMS / 128, FPD / 64);
    ctx_mma<<<gc, 256, CTX_SMEM>>>(b_attend);

    dim3 gg(NATOMS / 64, FPD / 64);
    gru_mma<<<gg, 256, GB_SMEM>>>(b_ih, b_hh, out);
}

// round 7
// speedup vs baseline: 1.8595x; 1.1260x over previous
#include <cuda_runtime.h>
#include <cuda_bf16.h>
#include <math.h>
#include <stdint.h>

// Problem constants
#define BQ   512
#define LQ   128
#define MQ   6
#define AD   39
#define BD   10
#define CD   49
#define FPD  256
#define NATOMS (BQ * LQ)   // 65536

// ---------------------------------------------------------------------------
// Device-global scratch (allocation-free rule)
// ---------------------------------------------------------------------------
__device__ __align__(16) float g_af[NATOMS * FPD];
__device__ __align__(16) float g_asum[NATOMS];
__device__ __align__(16) __nv_bfloat16 g_s_hi[NATOMS * FPD],  g_s_lo[NATOMS * FPD];
__device__ __align__(16) __nv_bfloat16 g_af_hi[NATOMS * FPD], g_af_lo[NATOMS * FPD];
__device__ __align__(16) __nv_bfloat16 g_cx_hi[NATOMS * FPD], g_cx_lo[NATOMS * FPD];
__device__ __align__(16) __nv_bfloat16 g_Wat_h[FPD * FPD],     g_Wat_l[FPD * FPD];
__device__ __align__(16) __nv_bfloat16 g_Wih_h[3 * FPD * FPD], g_Wih_l[3 * FPD * FPD];
__device__ __align__(16) __nv_bfloat16 g_Whh_h[3 * FPD * FPD], g_Whh_l[3 * FPD * FPD];

// ---------------------------------------------------------------------------
// Helpers
// ---------------------------------------------------------------------------
__device__ __forceinline__ uint32_t s2u(const void* p) {
    uint32_t a;
    asm("{ .reg .u64 t; cvta.to.shared.u64 t, %1; cvt.u32.u64 %0, t; }" : "=r"(a) : "l"(p));
    return a;
}
__device__ __forceinline__ void mma16816(float* c, const uint32_t* a, const uint32_t* b) {
    asm volatile("mma.sync.aligned.m16n8k16.row.col.f32.bf16.bf16.f32 "
        "{%0,%1,%2,%3}, {%4,%5,%6,%7}, {%8,%9}, {%0,%1,%2,%3};"
        : "+f"(c[0]), "+f"(c[1]), "+f"(c[2]), "+f"(c[3])
        : "r"(a[0]), "r"(a[1]), "r"(a[2]), "r"(a[3]), "r"(b[0]), "r"(b[1]));
}
__device__ __forceinline__ void ldm4(uint32_t* r, uint32_t addr) {
    asm volatile("ldmatrix.sync.aligned.m8n8.x4.shared.b16 {%0,%1,%2,%3}, [%4];"
        : "=r"(r[0]), "=r"(r[1]), "=r"(r[2]), "=r"(r[3]) : "r"(addr));
}
__device__ __forceinline__ void cpa16(uint32_t d, const void* s) {
    asm volatile("cp.async.cg.shared.global [%0], [%1], 16;" :: "r"(d), "l"(s) : "memory");
}
#define CP_COMMIT() asm volatile("cp.async.commit_group;" ::: "memory")
#define CP_WAIT1()  asm volatile("cp.async.wait_group 1;" ::: "memory")
#define CP_WAIT0()  asm volatile("cp.async.wait_group 0;" ::: "memory")

__device__ __forceinline__ float leakyf(float x) { return x > 0.f ? x : 0.01f * x; }
__device__ __forceinline__ float sigmf(float x)  { return 1.f / (1.f + expf(-x)); }
__device__ __forceinline__ void split2(float v, __nv_bfloat16& h, __nv_bfloat16& l) {
    h = __float2bfloat16(v);
    l = __float2bfloat16(v - __bfloat162float(h));
}
__device__ __forceinline__ uint32_t pk2(__nv_bfloat16 a, __nv_bfloat16 b) {
    return (uint32_t)__bfloat16_as_ushort(a) | ((uint32_t)__bfloat16_as_ushort(b) << 16);
}

// ---------------------------------------------------------------------------
// Kernel 0: split weights to bf16 hi/lo pairs
// ---------------------------------------------------------------------------
__global__ void prep_w(const float* __restrict__ Wat, const float* __restrict__ Wih,
                       const float* __restrict__ Whh) {
    int i = blockIdx.x * 256 + threadIdx.x;
    if (i < FPD * FPD)     split2(Wat[i], g_Wat_h[i], g_Wat_l[i]);
    if (i < 3 * FPD * FPD) {
        split2(Wih[i], g_Wih_h[i], g_Wih_l[i]);
        split2(Whh[i], g_Whh_h[i], g_Whh_l[i]);
    }
}

// ---------------------------------------------------------------------------
// Kernel 1: fused gather + projections + attention (2 atoms / iter, float4)
// (unchanged from R6 — passing at rel_err 2.5e-6)
// ---------------------------------------------------------------------------
#define K1_ATOMS 32
#define O_WA   0
#define O_WN   (AD * FPD)
#define O_WAL  (O_WN + CD * FPD)
#define O_ACTS (O_WAL + 2 * FPD)
#define O_AROW (O_ACTS + 12 * 56)
#define O_RED  (O_AROW + 80)
#define O_PADF (O_RED + 112)
#define O_IDX  (O_PADF + 12)
#define K1_SMEM ((O_IDX + 24) * 4)

__global__ void __launch_bounds__(256, 2) attn_kernel(
    const float* __restrict__ atom_list, const float* __restrict__ bond_list,
    const int*   __restrict__ adeg,      const int*   __restrict__ bdeg,
    const float* __restrict__ W_atom,    const float* __restrict__ b_atom,
    const float* __restrict__ W_nbr,     const float* __restrict__ b_nbr,
    const float* __restrict__ W_align,   const float* __restrict__ b_align)
{
    extern __shared__ float smem[];
    float* Wa   = smem + O_WA;
    float* Wn   = smem + O_WN;
    float* wal  = smem + O_WAL;
    float* acts = smem + O_ACTS;
    float* arow = smem + O_AROW;
    float* red  = smem + O_RED;
    float* padf = smem + O_PADF;
    int*   idx  = (int*)(smem + O_IDX);

    const int tid = threadIdx.x;
    const int f   = tid;

    for (int i = tid; i < AD * FPD; i += 256) {
        int ff = i / AD, k = i % AD;
        Wa[k * FPD + ff] = W_atom[i];
    }
    for (int i = tid; i < CD * FPD; i += 256) {
        int ff = i / CD, k = i % CD;
        Wn[k * FPD + ff] = W_nbr[i];
    }
    for (int i = tid; i < 2 * FPD; i += 256) wal[i] = W_align[i];

    const float ba  = b_atom[f];
    const float bn  = b_nbr[f];
    const float bal = b_align[0];
    __syncthreads();

    const float wal1 = wal[f];
    const float wal2 = wal[FPD + f];
    const int   warp = tid >> 5;
    const int   lane = tid & 31;
    const int   base = blockIdx.x * K1_ATOMS;

    for (int ai = 0; ai < K1_ATOMS; ai += 2) {
        const int atom0 = base + ai;
        const int bmol  = atom0 / LQ;

        __syncthreads();
        if (tid < 24) {
            int a = tid / 12, j = tid % 12;
            int atom = atom0 + a;
            if (j < MQ) {
                int ia = adeg[atom * MQ + j];
                idx[a * 12 + j] = ia;
                padf[a * 6 + j] = (ia == LQ - 1) ? 1.f : 0.f;
            } else {
                idx[a * 12 + j] = bdeg[atom * MQ + (j - MQ)];
            }
        }
        __syncthreads();
        for (int i = tid; i < 2 * (AD + MQ * CD); i += 256) {
            int a = i / 333, j = i % 333;
            if (j < AD) {
                arow[a * 40 + j] = atom_list[(atom0 + a) * AD + j];
            } else {
                int m = (j - AD) / CD, c = (j - AD) % CD;
                float v;
                if (c < AD) v = atom_list[(bmol * LQ + idx[a * 12 + m]) * AD + c];
                else        v = bond_list[(bmol * LQ + idx[a * 12 + 6 + m]) * BD + (c - AD)];
                acts[(a * 6 + m) * 56 + c] = v;
            }
        }
        __syncthreads();

        float af[2]; af[0] = ba; af[1] = ba;
        #pragma unroll
        for (int k0 = 0; k0 < 36; k0 += 4) {
            float w0 = Wa[(k0 + 0) * FPD + f], w1 = Wa[(k0 + 1) * FPD + f];
            float w2 = Wa[(k0 + 2) * FPD + f], w3 = Wa[(k0 + 3) * FPD + f];
            #pragma unroll
            for (int a = 0; a < 2; a++) {
                float4 x = *(const float4*)&arow[a * 40 + k0];
                af[a] += w0 * x.x + w1 * x.y + w2 * x.z + w3 * x.w;
            }
        }
        {
            float w0 = Wa[36 * FPD + f], w1 = Wa[37 * FPD + f], w2 = Wa[38 * FPD + f];
            #pragma unroll
            for (int a = 0; a < 2; a++)
                af[a] += w0 * arow[a * 40 + 36] + w1 * arow[a * 40 + 37] + w2 * arow[a * 40 + 38];
        }
        af[0] = leakyf(af[0]); af[1] = leakyf(af[1]);

        float nf[2][MQ];
        #pragma unroll
        for (int a = 0; a < 2; a++)
            #pragma unroll
            for (int m = 0; m < MQ; m++) nf[a][m] = bn;
        #pragma unroll 4
        for (int k0 = 0; k0 < 48; k0 += 4) {
            float w0 = Wn[(k0 + 0) * FPD + f], w1 = Wn[(k0 + 1) * FPD + f];
            float w2 = Wn[(k0 + 2) * FPD + f], w3 = Wn[(k0 + 3) * FPD + f];
            #pragma unroll
            for (int a = 0; a < 2; a++)
                #pragma unroll
                for (int m = 0; m < MQ; m++) {
                    float4 x = *(const float4*)&acts[(a * 6 + m) * 56 + k0];
                    nf[a][m] += w0 * x.x + w1 * x.y + w2 * x.z + w3 * x.w;
                }
        }
        {
            float w = Wn[48 * FPD + f];
            #pragma unroll
            for (int a = 0; a < 2; a++)
                #pragma unroll
                for (int m = 0; m < MQ; m++)
                    nf[a][m] += w * acts[(a * 6 + m) * 56 + 48];
        }
        #pragma unroll
        for (int a = 0; a < 2; a++)
            #pragma unroll
            for (int m = 0; m < MQ; m++) nf[a][m] = leakyf(nf[a][m]);

        float v[14];
        #pragma unroll
        for (int a = 0; a < 2; a++) {
            v[a * 7] = af[a] * wal1;
            #pragma unroll
            for (int m = 0; m < MQ; m++) v[a * 7 + 1 + m] = nf[a][m] * wal2;
        }
        #pragma unroll
        for (int off = 16; off > 0; off >>= 1)
            #pragma unroll
            for (int j = 0; j < 14; j++)
                v[j] += __shfl_down_sync(0xffffffffu, v[j], off);
        if (lane == 0)
            #pragma unroll
            for (int j = 0; j < 14; j++) red[warp * 14 + j] = v[j];
        __syncthreads();

        #pragma unroll
        for (int a = 0; a < 2; a++) {
            float sums[7];
            #pragma unroll
            for (int j = 0; j < 7; j++) {
                float s = 0.f;
                #pragma unroll
                for (int w = 0; w < 8; w++) s += red[w * 14 + a * 7 + j];
                sums[j] = s;
            }
            float sc[MQ], mx = -INFINITY;
            #pragma unroll
            for (int m = 0; m < MQ; m++) {
                float s = leakyf(sums[0] + sums[1 + m] + bal);
                if (padf[a * 6 + m] > 0.5f) s += -9e8f;
                sc[m] = s;
                mx = fmaxf(mx, s);
            }
            float e[MQ], se = 0.f;
            #pragma unroll
            for (int m = 0; m < MQ; m++) { e[m] = expf(sc[m] - mx); se += e[m]; }
            float inv = 1.f / se;
            float asum = 0.f, sf = 0.f;
            #pragma unroll
            for (int m = 0; m < MQ; m++) {
                float aw = e[m] * inv;
                if (padf[a * 6 + m] > 0.5f) aw = 0.f;
                asum += aw;
                sf   += aw * nf[a][m];
            }
            const int atom = atom0 + a;
            const int o = atom * FPD + f;
            g_af[o] = af[a];
            split2(af[a], g_af_hi[o], g_af_lo[o]);
            split2(sf,    g_s_hi[o],  g_s_lo[o]);
            if (tid == 0) g_asum[atom] = asum;
        }
    }
}

// ---------------------------------------------------------------------------
// Kernel 2a: ctx = elu( s @ W_att^T + asum*b ), mma.sync + ldmatrix (R6 version)
// ---------------------------------------------------------------------------
#define CTX_AH 0
#define CTX_AL 10240
#define CTX_BH 20480
#define CTX_BL 25600
#define CTX_BUF 30720
#define CTX_BATT (2 * CTX_BUF)
#define CTX_SMEM (CTX_BATT + 256)

__global__ void __launch_bounds__(256) ctx_mma(const float* __restrict__ batt_g)
{
    extern __shared__ char sm[];
    const uint32_t sb = s2u(sm);
    float* sbatt = (float*)(sm + CTX_BATT);
    const int tid = threadIdx.x, wid = tid >> 5, lane = tid & 31;
    const int m0 = blockIdx.x * 128, n0 = blockIdx.y * 64;
    const int Moff = (wid & 3) * 32, Noff = (wid >> 2) * 32;

    if (tid < 64) sbatt[tid] = batt_g[n0 + tid];

    const int r_ = tid >> 2, q_ = tid & 3;
    const uint32_t soff = (uint32_t)(r_ * 80 + q_ * 16);
    const int aoff0 = (m0 + r_) * FPD + q_ * 8;
    const int aoff1 = (m0 + 64 + r_) * FPD + q_ * 8;
    const int boff  = (n0 + r_) * FPD + q_ * 8;

    const uint32_t a_lo = (uint32_t)((lane & 15) * 80 + (lane >> 4) * 16);
    const uint32_t b_lo = (uint32_t)(((lane & 7) + ((lane >> 4) << 3)) * 80 + ((lane >> 3) & 1) * 16);

    const int row0 = lane >> 2, qb = lane & 3;
    float acc[2][4][4] = {};

    cpa16(sb + CTX_AH + soff,        g_s_hi + aoff0);
    cpa16(sb + CTX_AH + 5120 + soff, g_s_hi + aoff1);
    cpa16(sb + CTX_AL + soff,        g_s_lo + aoff0);
    cpa16(sb + CTX_AL + 5120 + soff, g_s_lo + aoff1);
    cpa16(sb + CTX_BH + soff, g_Wat_h + boff);
    cpa16(sb + CTX_BL + soff, g_Wat_l + boff);
    CP_COMMIT();

    for (int c = 0; c < 8; c++) {
        if (c < 7) {
            const int k0 = (c + 1) * 32;
            const uint32_t bo = ((c + 1) & 1) * CTX_BUF;
            cpa16(sb + bo + CTX_AH + soff,        g_s_hi + aoff0 + k0);
            cpa16(sb + bo + CTX_AH + 5120 + soff, g_s_hi + aoff1 + k0);
            cpa16(sb + bo + CTX_AL + soff,        g_s_lo + aoff0 + k0);
            cpa16(sb + bo + CTX_AL + 5120 + soff, g_s_lo + aoff1 + k0);
            cpa16(sb + bo + CTX_BH + soff, g_Wat_h + boff + k0);
            cpa16(sb + bo + CTX_BL + soff, g_Wat_l + boff + k0);
            CP_COMMIT();
            CP_WAIT1();
        } else {
            CP_WAIT0();
        }
        __syncthreads();
        const uint32_t bb = sb + (c & 1) * CTX_BUF;
        #pragma unroll
        for (int ks = 0; ks < 2; ks++) {
            uint32_t ah[2][4], al[2][4];
            #pragma unroll
            for (int mt = 0; mt < 2; mt++) {
                uint32_t ao = (uint32_t)((Moff + mt * 16) * 80) + a_lo + ks * 32;
                ldm4(ah[mt], bb + CTX_AH + ao);
                ldm4(al[mt], bb + CTX_AL + ao);
            }
            uint32_t bh[2][4], bl[2][4];
            #pragma unroll
            for (int p = 0; p < 2; p++) {
                uint32_t bo2 = (uint32_t)((Noff + p * 16) * 80) + b_lo + ks * 32;
                ldm4(bh[p], bb + CTX_BH + bo2);
                ldm4(bl[p], bb + CTX_BL + bo2);
            }
            #pragma unroll
            for (int mt = 0; mt < 2; mt++)
                #pragma unroll
                for (int nt = 0; nt < 4; nt++) {
                    const uint32_t* Bh = &bh[nt >> 1][(nt & 1) * 2];
                    const uint32_t* Bl = &bl[nt >> 1][(nt & 1) * 2];
                    mma16816(acc[mt][nt], ah[mt], Bh);
                    mma16816(acc[mt][nt], ah[mt], Bl);
                    mma16816(acc[mt][nt], al[mt], Bh);
                }
        }
        __syncthreads();
    }

    #pragma unroll
    for (int mt = 0; mt < 2; mt++) {
        int r0 = m0 + Moff + mt * 16 + row0;
        float as0 = g_asum[r0], as1 = g_asum[r0 + 8];
        #pragma unroll
        for (int nt = 0; nt < 4; nt++) {
            int cl = Noff + nt * 8 + qb * 2;
            int col = n0 + cl;
            float b0 = sbatt[cl], b1 = sbatt[cl + 1];
            float t00 = acc[mt][nt][0] + as0 * b0, t01 = acc[mt][nt][1] + as0 * b1;
            float t10 = acc[mt][nt][2] + as1 * b0, t11 = acc[mt][nt][3] + as1 * b1;
            t00 = t00 > 0.f ? t00 : expm1f(t00);
            t01 = t01 > 0.f ? t01 : expm1f(t01);
            t10 = t10 > 0.f ? t10 : expm1f(t10);
            t11 = t11 > 0.f ? t11 : expm1f(t11);
            __nv_bfloat16 h0, l0, h1, l1;
            split2(t00, h0, l0); split2(t01, h1, l1);
            *(uint32_t*)&g_cx_hi[r0 * FPD + col] = pk2(h0, h1);
            *(uint32_t*)&g_cx_lo[r0 * FPD + col] = pk2(l0, l1);
            split2(t10, h0, l0); split2(t11, h1, l1);
            *(uint32_t*)&g_cx_hi[(r0 + 8) * FPD + col] = pk2(h0, h1);
            *(uint32_t*)&g_cx_lo[(r0 + 8) * FPD + col] = pk2(l0, l1);
        }
    }
}

// ---------------------------------------------------------------------------
// Kernel 2b: GRU — 512 threads (16 warps, 4x4), warp tile 16x16 x 6 gates.
// KC=32 (80B rows), double-buffer, acc=48 regs/thread -> 16 resident warps.
// Tiles: 0 cx_hi, 1 cx_lo, 2 af_hi, 3 af_lo, 4+2g+half = gate g hi/lo.
// ---------------------------------------------------------------------------
#define GT      5120                 // 64 rows x 80B
#define GB_B    (4 * GT)
#define GB_BUF  (16 * GT)            // 81920
#define GB_BIAS (2 * GB_BUF)         // 163840
#define GB_SMEM (GB_BIAS + 1536)

__global__ void __launch_bounds__(512) gru_mma(
    const float* __restrict__ b_ih, const float* __restrict__ b_hh,
    float* __restrict__ out)
{
    extern __shared__ char sm[];
    const uint32_t sb = s2u(sm);
    float* sbias = (float*)(sm + GB_BIAS);
    const int tid = threadIdx.x, wid = tid >> 5, lane = tid & 31;
    const int m0 = blockIdx.x * 64, f0 = blockIdx.y * 64;
    const int Moff = (wid >> 2) * 16, Noff = (wid & 3) * 16;

    if (tid < 384) {
        int g = tid >> 6, fl = tid & 63;
        sbias[tid] = (g < 3) ? b_ih[g * FPD + f0 + fl] : b_hh[(g - 3) * FPD + f0 + fl];
    }

    // staging: half = hi/lo family, each thread loads 8 tiles (one per pair)
    const int half = tid >> 8;           // 0: hi tiles, 1: lo tiles
    const int r_   = (tid & 255) >> 2;   // row 0..63
    const int s_   = tid & 3;            // 16B segment (64B data per row)
    const uint32_t soff = (uint32_t)(r_ * 80 + s_ * 16);
    const int aoff  = (m0 + r_) * FPD + s_ * 8;
    const int wrow0 = (0 * FPD + f0 + r_) * FPD + s_ * 8;
    const int wrow1 = (1 * FPD + f0 + r_) * FPD + s_ * 8;
    const int wrow2 = (2 * FPD + f0 + r_) * FPD + s_ * 8;

    const __nv_bfloat16* srcH[8] = { g_cx_hi, g_af_hi, g_Wih_h, g_Wih_h, g_Wih_h,
                                     g_Whh_h, g_Whh_h, g_Whh_h };
    const __nv_bfloat16* srcL[8] = { g_cx_lo, g_af_lo, g_Wih_l, g_Wih_l, g_Wih_l,
                                     g_Whh_l, g_Whh_l, g_Whh_l };
    const int prow[8] = { aoff, aoff, wrow0, wrow1, wrow2, wrow0, wrow1, wrow2 };

    const uint32_t a_lo = (uint32_t)((lane & 15) * 80 + (lane >> 4) * 16);
    const uint32_t b_lo = (uint32_t)(((lane & 7) + ((lane >> 4) << 3)) * 80 + ((lane >> 3) & 1) * 16);

    const int row0 = lane >> 2, qb = lane & 3;
    float acc[6][2][4] = {};

    // prologue: stage chunk 0
    #pragma unroll
    for (int j = 0; j < 8; j++) {
        const __nv_bfloat16* p = half ? srcL[j] : srcH[j];
        cpa16(sb + (uint32_t)((2 * j + half) * GT) + soff, p + prow[j]);
    }
    CP_COMMIT();

    for (int c = 0; c < 8; c++) {
        if (c < 7) {
            const int k0 = (c + 1) * 32;
            const uint32_t bs = sb + ((c + 1) & 1) * GB_BUF;
            #pragma unroll
            for (int j = 0; j < 8; j++) {
                const __nv_bfloat16* p = half ? srcL[j] : srcH[j];
                cpa16(bs + (uint32_t)((2 * j + half) * GT) + soff, p + prow[j] + k0);
            }
            CP_COMMIT();
            CP_WAIT1();
        } else {
            CP_WAIT0();
        }
        __syncthreads();
        const uint32_t bb = sb + (c & 1) * GB_BUF;
        #pragma unroll
        for (int ks = 0; ks < 2; ks++) {
            uint32_t Ah[2][4], Al[2][4];   // [am: 0=ctx 1=af]
            #pragma unroll
            for (int am = 0; am < 2; am++) {
                uint32_t ao = (uint32_t)(Moff * 80) + a_lo + ks * 32;
                ldm4(Ah[am], bb + (uint32_t)((am * 2) * GT) + ao);
                ldm4(Al[am], bb + (uint32_t)((am * 2 + 1) * GT) + ao);
            }
            #pragma unroll
            for (int g = 0; g < 6; g++) {
                uint32_t bhf[4], blf[4];
                uint32_t bo2 = (uint32_t)(Noff * 80) + b_lo + ks * 32;
                ldm4(bhf, bb + GB_B + (uint32_t)((g * 2) * GT) + bo2);
                ldm4(blf, bb + GB_B + (uint32_t)((g * 2 + 1) * GT) + bo2);
                const int am = (g < 3) ? 0 : 1;
                #pragma unroll
                for (int nt = 0; nt < 2; nt++) {
                    const uint32_t* Bh = &bhf[nt * 2];
                    const uint32_t* Bl = &blf[nt * 2];
                    mma16816(acc[g][nt], Ah[am], Bh);
                    mma16816(acc[g][nt], Ah[am], Bl);
                    mma16816(acc[g][nt], Al[am], Bh);
                }
            }
        }
        __syncthreads();
    }

    // fused GRU + ReLU epilogue (0=i_r 1=i_z 2=i_n 3=h_r 4=h_z 5=h_n)
    #pragma unroll
    for (int rp = 0; rp < 2; rp++) {
        int row = m0 + Moff + row0 + rp * 8;
        #pragma unroll
        for (int nt = 0; nt < 2; nt++) {
            int cl = Noff + nt * 8 + qb * 2;
            int colG = f0 + cl;
            float o2[2];
            #pragma unroll
            for (int j = 0; j < 2; j++) {
                int ci = rp * 2 + j;
                float ir  = acc[0][nt][ci] + sbias[cl + j];
                float iz  = acc[1][nt][ci] + sbias[64 + cl + j];
                float in_ = acc[2][nt][ci] + sbias[128 + cl + j];
                float hr  = acc[3][nt][ci] + sbias[192 + cl + j];
                float hz  = acc[4][nt][ci] + sbias[256 + cl + j];
                float hn  = acc[5][nt][ci] + sbias[320 + cl + j];
                float r = sigmf(ir + hr), z = sigmf(iz + hz);
                float n = tanhf(in_ + r * hn);
                float h = g_af[row * FPD + colG + j];
                o2[j] = fmaxf((1.f - z) * n + z * h, 0.f);
            }
            *(float2*)&out[row * FPD + colG] = make_float2(o2[0], o2[1]);
        }
    }
}

// ---------------------------------------------------------------------------
// Launcher
// ---------------------------------------------------------------------------
extern "C" void kernel_launch(void* const* d_in, const int* in_sizes, int n_in,
                              void* d_out, int out_size)
{
    const float* atom_list = (const float*)d_in[0];
    const float* bond_list = (const float*)d_in[1];
    const int*   adeg      = (const int*)  d_in[2];
    const int*   bdeg      = (const int*)  d_in[3];
    const float* W_atom   = (const float*)d_in[5];
    const float* b_atom   = (const float*)d_in[6];
    const float* W_nbr    = (const float*)d_in[7];
    const float* b_nbr    = (const float*)d_in[8];
    const float* W_align  = (const float*)d_in[9];
    const float* b_align  = (const float*)d_in[10];
    const float* W_attend = (const float*)d_in[11];
    const float* b_attend = (const float*)d_in[12];
    const float* W_ih     = (const float*)d_in[13];
    const float* b_ih     = (const float*)d_in[14];
    const float* W_hh     = (const float*)d_in[15];
    const float* b_hh     = (const float*)d_in[16];
    float* out = (float*)d_out;
    (void)in_sizes; (void)n_in; (void)out_size;

    cudaFuncSetAttribute(attn_kernel, cudaFuncAttributeMaxDynamicSharedMemorySize, K1_SMEM);
    cudaFuncSetAttribute(ctx_mma,     cudaFuncAttributeMaxDynamicSharedMemorySize, CTX_SMEM);
    cudaFuncSetAttribute(gru_mma,     cudaFuncAttributeMaxDynamicSharedMemorySize, GB_SMEM);

    prep_w<<<(3 * FPD * FPD + 255) / 256, 256>>>(W_attend, W_ih, W_hh);

    attn_kernel<<<NATOMS / K1_ATOMS, 256, K1_SMEM>>>(
        atom_list, bond_list, adeg, bdeg,
        W_atom, b_atom, W_nbr, b_nbr, W_align, b_align);

    dim3 gc(NATOMS / 128, FPD / 64);
    ctx_mma<<<gc, 256, CTX_SMEM>>>(b_attend);

    dim3 gg(NATOMS / 64, FPD / 64);
    gru_mma<<<gg, 512, GB_SMEM>>>(b_ih, b_hh, out);
}